// round 16
// baseline (speedup 1.0000x reference)
#include <cuda_runtime.h>
#include <math.h>
#include <float.h>
#include <stdint.h>

// ---------------------------------------------------------------------------
// GCN: sparse-extract adjacency (overlapped with L0 GEMM) -> per layer
//      [split-K f32x2 GEMM (4-way L0, 2-way HxH), reduce, sparse aggregate]
//      with agg->gemm junctions software-pipelined across two streams
//      -> max/mean pool -> MLP head.
// N <= 10000, DIN = 1024, H = 256, NC = 3
// ---------------------------------------------------------------------------

#define MAXN   10112
#define MAXNZ  128
#define HDIM   256
#define POOLB  256

__device__ float g_dinv[MAXN];
__device__ int   g_cnt[MAXN];
__device__ int   g_col[MAXN * MAXNZ];
__device__ float g_val[MAXN * MAXNZ];
__device__ float g_y [MAXN * HDIM];     // split 0 partial -> summed Y
__device__ float g_y2[MAXN * HDIM];     // split 1 partial
__device__ float g_y3[MAXN * HDIM];     // split 2 partial
__device__ float g_y4[MAXN * HDIM];     // split 3 partial
__device__ float g_x [MAXN * HDIM];     // layer activations
__device__ float g_pmax[POOLB * HDIM];
__device__ float g_psum[POOLB * HDIM];

typedef unsigned long long ull;

__device__ __forceinline__ void fma2(ull& d, ull a, ull b)
{
    asm("fma.rn.f32x2 %0, %1, %2, %0;" : "+l"(d) : "l"(a), "l"(b));
}
__device__ __forceinline__ ull pack2(float x, float y)
{
    ull r;
    asm("mov.b64 %0, {%1, %2};" : "=l"(r) : "f"(x), "f"(y));
    return r;
}
__device__ __forceinline__ void unpack2(ull v, float& x, float& y)
{
    asm("mov.b64 {%0, %1}, %2;" : "=f"(x), "=f"(y) : "l"(v));
}

// ---------------------------------------------------------------------------
// Kernel 1: row scan -> degree (dinv) + nonzero extraction
// ---------------------------------------------------------------------------
__global__ void extract_kernel(const float* __restrict__ adj, int N)
{
    int row = blockIdx.x;
    int tid = threadIdx.x;
    __shared__ int cnt;
    __shared__ float wsum[8];
    if (tid == 0) cnt = 0;
    __syncthreads();

    const float4* a4 = (const float4*)(adj + (size_t)row * N);
    int n4 = N >> 2;
    float sum = 0.0f;

    for (int i = tid; i < n4; i += 256) {
        float4 v = a4[i];
        sum += (v.x + v.y) + (v.z + v.w);
        int j = i << 2;
        if (v.x != 0.0f && j + 0 != row) { int o = atomicAdd(&cnt, 1); if (o < MAXNZ) { g_col[row*MAXNZ+o] = j+0; g_val[row*MAXNZ+o] = v.x; } }
        if (v.y != 0.0f && j + 1 != row) { int o = atomicAdd(&cnt, 1); if (o < MAXNZ) { g_col[row*MAXNZ+o] = j+1; g_val[row*MAXNZ+o] = v.y; } }
        if (v.z != 0.0f && j + 2 != row) { int o = atomicAdd(&cnt, 1); if (o < MAXNZ) { g_col[row*MAXNZ+o] = j+2; g_val[row*MAXNZ+o] = v.z; } }
        if (v.w != 0.0f && j + 3 != row) { int o = atomicAdd(&cnt, 1); if (o < MAXNZ) { g_col[row*MAXNZ+o] = j+3; g_val[row*MAXNZ+o] = v.w; } }
    }
    for (int j = (n4 << 2) + tid; j < N; j += 256) {
        float v = adj[(size_t)row * N + j];
        sum += v;
        if (v != 0.0f && j != row) { int o = atomicAdd(&cnt, 1); if (o < MAXNZ) { g_col[row*MAXNZ+o] = j; g_val[row*MAXNZ+o] = v; } }
    }

    #pragma unroll
    for (int s = 16; s > 0; s >>= 1) sum += __shfl_xor_sync(0xffffffffu, sum, s);
    if ((tid & 31) == 0) wsum[tid >> 5] = sum;
    __syncthreads();
    if (tid == 0) {
        float t = 0.0f;
        #pragma unroll
        for (int w = 0; w < 8; w++) t += wsum[w];
        g_cnt[row]  = cnt < MAXNZ ? cnt : MAXNZ;
        g_dinv[row] = rsqrtf(t + 1.0f);
    }
}

// ---------------------------------------------------------------------------
// Kernel 2: split-K GEMM partials (split count = gridDim.z), row range
// [mStart, mStart + 64*gridDim.y). Tile 64x128, BK=16, 128 threads,
// per-thread 8x8, double-buffered, packed f32x2 FMA (champion inner loop).
// ---------------------------------------------------------------------------
#define ABK 16

__global__ void __launch_bounds__(128, 3)
gemm_f32x2_kernel(const float* __restrict__ Aext, const float* __restrict__ B,
                  int M, int Ktot, int mStart)
{
    __shared__ float As[2][ABK][68];    // [k][m]
    __shared__ float Bs[2][ABK][132];   // [k][n]

    const float* A = Aext ? Aext : g_x;
    int nsplit = gridDim.z;
    int KL   = Ktot / nsplit;
    int kOff = blockIdx.z * KL;
    float* Cout = (blockIdx.z == 0) ? g_y :
                  (blockIdx.z == 1) ? g_y2 :
                  (blockIdx.z == 2) ? g_y3 : g_y4;

    int tid = threadIdx.x;
    int tx = tid & 15;      // cols 4tx..+3 and 64+4tx..+3
    int ty = tid >> 4;      // rows 8ty..+7
    int bm = mStart + blockIdx.y * 64;
    int bn = blockIdx.x * 128;

    ull acc[8][4];
    #pragma unroll
    for (int i = 0; i < 8; i++)
        #pragma unroll
        for (int j = 0; j < 4; j++) acc[i][j] = pack2(0.0f, 0.0f);

    // global-load mapping
    int ar = tid >> 1;             // 0..63
    int ak = (tid & 1) << 3;       // 0 or 8
    int gm = bm + ar;
    bool mv = gm < M;
    const float* Arow = A + (size_t)(mv ? gm : 0) * Ktot + kOff;
    const float* Bbase = B + (size_t)kOff * HDIM;

    int bk = tid >> 5;             // 0..3: rows bk, bk+4, bk+8, bk+12
    int bc = (tid & 31) << 2;      // 0..124

    // prologue
    {
        float4 a0 = mv ? *(const float4*)&Arow[ak]     : make_float4(0,0,0,0);
        float4 a1 = mv ? *(const float4*)&Arow[ak + 4] : make_float4(0,0,0,0);
        As[0][ak+0][ar] = a0.x; As[0][ak+1][ar] = a0.y;
        As[0][ak+2][ar] = a0.z; As[0][ak+3][ar] = a0.w;
        As[0][ak+4][ar] = a1.x; As[0][ak+5][ar] = a1.y;
        As[0][ak+6][ar] = a1.z; As[0][ak+7][ar] = a1.w;
        #pragma unroll
        for (int t = 0; t < 4; t++)
            *(float4*)&Bs[0][bk + 4*t][bc] =
                *(const float4*)&Bbase[(size_t)(bk + 4*t) * HDIM + bn + bc];
    }
    __syncthreads();

    int buf = 0;
    for (int k0 = ABK; k0 < KL; k0 += ABK) {
        float4 aN0 = mv ? *(const float4*)&Arow[k0 + ak]     : make_float4(0,0,0,0);
        float4 aN1 = mv ? *(const float4*)&Arow[k0 + ak + 4] : make_float4(0,0,0,0);
        float4 bN[4];
        #pragma unroll
        for (int t = 0; t < 4; t++)
            bN[t] = *(const float4*)&Bbase[(size_t)(k0 + bk + 4*t) * HDIM + bn + bc];

        #pragma unroll
        for (int k = 0; k < ABK; k++) {
            float4 av0 = *(const float4*)&As[buf][k][ty * 8];
            float4 av1 = *(const float4*)&As[buf][k][ty * 8 + 4];
            float4 b0  = *(const float4*)&Bs[buf][k][tx * 4];
            float4 b1  = *(const float4*)&Bs[buf][k][64 + tx * 4];
            ull bp0 = pack2(b0.x, b0.y);
            ull bp1 = pack2(b0.z, b0.w);
            ull bp2 = pack2(b1.x, b1.y);
            ull bp3 = pack2(b1.z, b1.w);
            float arr[8] = {av0.x, av0.y, av0.z, av0.w, av1.x, av1.y, av1.z, av1.w};
            #pragma unroll
            for (int i = 0; i < 8; i++) {
                ull ap = pack2(arr[i], arr[i]);
                fma2(acc[i][0], ap, bp0);
                fma2(acc[i][1], ap, bp1);
                fma2(acc[i][2], ap, bp2);
                fma2(acc[i][3], ap, bp3);
            }
        }

        As[buf^1][ak+0][ar] = aN0.x; As[buf^1][ak+1][ar] = aN0.y;
        As[buf^1][ak+2][ar] = aN0.z; As[buf^1][ak+3][ar] = aN0.w;
        As[buf^1][ak+4][ar] = aN1.x; As[buf^1][ak+5][ar] = aN1.y;
        As[buf^1][ak+6][ar] = aN1.z; As[buf^1][ak+7][ar] = aN1.w;
        #pragma unroll
        for (int t = 0; t < 4; t++)
            *(float4*)&Bs[buf^1][bk + 4*t][bc] = bN[t];
        __syncthreads();
        buf ^= 1;
    }

    // final tile
    #pragma unroll
    for (int k = 0; k < ABK; k++) {
        float4 av0 = *(const float4*)&As[buf][k][ty * 8];
        float4 av1 = *(const float4*)&As[buf][k][ty * 8 + 4];
        float4 b0  = *(const float4*)&Bs[buf][k][tx * 4];
        float4 b1  = *(const float4*)&Bs[buf][k][64 + tx * 4];
        ull bp0 = pack2(b0.x, b0.y);
        ull bp1 = pack2(b0.z, b0.w);
        ull bp2 = pack2(b1.x, b1.y);
        ull bp3 = pack2(b1.z, b1.w);
        float arr[8] = {av0.x, av0.y, av0.z, av0.w, av1.x, av1.y, av1.z, av1.w};
        #pragma unroll
        for (int i = 0; i < 8; i++) {
            ull ap = pack2(arr[i], arr[i]);
            fma2(acc[i][0], ap, bp0);
            fma2(acc[i][1], ap, bp1);
            fma2(acc[i][2], ap, bp2);
            fma2(acc[i][3], ap, bp3);
        }
    }

    // epilogue
    #pragma unroll
    for (int i = 0; i < 8; i++) {
        int m = bm + ty * 8 + i;
        if (m >= M) continue;
        float o0, o1, o2, o3, o4, o5, o6, o7;
        unpack2(acc[i][0], o0, o1);
        unpack2(acc[i][1], o2, o3);
        unpack2(acc[i][2], o4, o5);
        unpack2(acc[i][3], o6, o7);
        float* dst = &Cout[(size_t)m * HDIM + bn];
        *(float4*)(dst + tx * 4)      = make_float4(o0, o1, o2, o3);
        *(float4*)(dst + 64 + tx * 4) = make_float4(o4, o5, o6, o7);
    }
}

// ---------------------------------------------------------------------------
// Kernel 2b: reduce split-K partials (fixed summation order, deterministic)
// ---------------------------------------------------------------------------
__global__ void reduce_kernel(int total4, int nsplit)
{
    int i = blockIdx.x * blockDim.x + threadIdx.x;
    if (i >= total4) return;
    float4 a = ((const float4*)g_y)[i];
    float4 b = ((const float4*)g_y2)[i];
    if (nsplit == 4) {
        float4 c = ((const float4*)g_y3)[i];
        float4 d = ((const float4*)g_y4)[i];
        a.x = (a.x + b.x) + (c.x + d.x);
        a.y = (a.y + b.y) + (c.y + d.y);
        a.z = (a.z + b.z) + (c.z + d.z);
        a.w = (a.w + b.w) + (c.w + d.w);
    } else {
        a.x += b.x; a.y += b.y; a.z += b.z; a.w += b.w;
    }
    ((float4*)g_y)[i] = a;
}

// ---------------------------------------------------------------------------
// Kernel 3: x'[i] = relu( dinv_i*( dinv_i*Y_i + sum val*dinv_j*Y_j ) + b )
// Row range [rowStart, rowStart + gridDim.x).
// ---------------------------------------------------------------------------
__global__ void aggregate_kernel(const float* __restrict__ bias, int rowStart)
{
    int i = rowStart + blockIdx.x;
    int c = threadIdx.x;            // 0..63
    const float4* y4 = (const float4*)g_y;
    float si = g_dinv[i];
    float4 self = y4[(size_t)i * 64 + c];
    float4 acc;
    acc.x = si * self.x; acc.y = si * self.y;
    acc.z = si * self.z; acc.w = si * self.w;

    int cnt = g_cnt[i];
    const int*   cols = &g_col[i * MAXNZ];
    const float* vals = &g_val[i * MAXNZ];

    int e = 0;
    for (; e + 4 <= cnt; e += 4) {
        int   c0 = cols[e],   c1 = cols[e+1], c2 = cols[e+2], c3 = cols[e+3];
        float v0 = vals[e]   * g_dinv[c0];
        float v1 = vals[e+1] * g_dinv[c1];
        float v2 = vals[e+2] * g_dinv[c2];
        float v3 = vals[e+3] * g_dinv[c3];
        float4 y0 = y4[(size_t)c0 * 64 + c];
        float4 y1 = y4[(size_t)c1 * 64 + c];
        float4 y2 = y4[(size_t)c2 * 64 + c];
        float4 y3 = y4[(size_t)c3 * 64 + c];
        acc.x += (v0*y0.x + v1*y1.x) + (v2*y2.x + v3*y3.x);
        acc.y += (v0*y0.y + v1*y1.y) + (v2*y2.y + v3*y3.y);
        acc.z += (v0*y0.z + v1*y1.z) + (v2*y2.z + v3*y3.z);
        acc.w += (v0*y0.w + v1*y1.w) + (v2*y2.w + v3*y3.w);
    }
    for (; e < cnt; e++) {
        int c0 = cols[e];
        float v0 = vals[e] * g_dinv[c0];
        float4 y0 = y4[(size_t)c0 * 64 + c];
        acc.x += v0*y0.x; acc.y += v0*y0.y; acc.z += v0*y0.z; acc.w += v0*y0.w;
    }

    float4 b = ((const float4*)bias)[c];
    float4 r;
    r.x = fmaxf(si*acc.x + b.x, 0.0f);
    r.y = fmaxf(si*acc.y + b.y, 0.0f);
    r.z = fmaxf(si*acc.z + b.z, 0.0f);
    r.w = fmaxf(si*acc.w + b.w, 0.0f);
    ((float4*)g_x)[(size_t)i * 64 + c] = r;
}

// ---------------------------------------------------------------------------
// Kernel 4: partial max/sum pool over rows of g_x (256 blocks)
// ---------------------------------------------------------------------------
__global__ void pool_partial_kernel(int N)
{
    int c = threadIdx.x;
    float mx = -FLT_MAX;
    float sm = 0.0f;
    for (int r = blockIdx.x; r < N; r += POOLB) {
        float v = g_x[(size_t)r * HDIM + c];
        mx = fmaxf(mx, v);
        sm += v;
    }
    g_pmax[blockIdx.x * HDIM + c] = mx;
    g_psum[blockIdx.x * HDIM + c] = sm;
}

// ---------------------------------------------------------------------------
// Kernel 5: finish pooling + MLP head (single block, 512 threads, fixed
// k-splits with deterministic smem reductions)
// ---------------------------------------------------------------------------
__global__ void pool_mlp_kernel(const float* __restrict__ C1w, const float* __restrict__ c1b,
                                const float* __restrict__ C2w, const float* __restrict__ c2b,
                                const float* __restrict__ C3w, const float* __restrict__ c3b,
                                float* __restrict__ out, int N)
{
    __shared__ float g[2 * HDIM];     // [max | mean]
    __shared__ float s0[512];
    __shared__ float s1[512];
    __shared__ float h1[HDIM];
    __shared__ float h2[HDIM / 2];
    int tid = threadIdx.x;
    int c = tid & 255;
    int half = tid >> 8;              // 0..1

    // finish pooling: each half scans 128 partial blocks
    float mx = -FLT_MAX, sm = 0.0f;
    for (int w = half * 128; w < half * 128 + 128; w++) {
        mx = fmaxf(mx, g_pmax[w * HDIM + c]);
        sm += g_psum[w * HDIM + c];
    }
    s0[tid] = mx; s1[tid] = sm;
    __syncthreads();
    if (half == 0) {
        g[c]        = fmaxf(s0[c], s0[c + 256]);
        g[HDIM + c] = (s1[c] + s1[c + 256]) / (float)N;
    }
    __syncthreads();

    // h1 = relu(g @ C1w + c1b): 2-way k-split (256 each)
    {
        float a = 0.0f;
        #pragma unroll 8
        for (int k = half * 256; k < half * 256 + 256; k++)
            a += g[k] * C1w[(size_t)k * HDIM + c];
        s0[tid] = a;
    }
    __syncthreads();
    if (half == 0) h1[c] = fmaxf((s0[c] + s0[c + 256]) + c1b[c], 0.0f);
    __syncthreads();

    // h2 = relu(h1 @ C2w + c2b): 128 cols, 4-way k-split (64 each)
    {
        int c2 = tid & 127, q = tid >> 7;   // q 0..3
        float a2 = 0.0f;
        #pragma unroll 8
        for (int k = q * 64; k < q * 64 + 64; k++)
            a2 += h1[k] * C2w[(size_t)k * (HDIM / 2) + c2];
        s1[q * 128 + c2] = a2;
    }
    __syncthreads();
    if (tid < HDIM / 2)
        h2[tid] = fmaxf(((s1[tid] + s1[128 + tid]) + (s1[256 + tid] + s1[384 + tid]))
                        + c2b[tid], 0.0f);
    __syncthreads();

    // out = h2 @ C3w + c3b
    if (tid < 3) {
        float a3 = c3b[tid];
        #pragma unroll 8
        for (int k = 0; k < HDIM / 2; k++)
            a3 += h2[k] * C3w[(size_t)k * 3 + tid];
        out[tid] = a3;
    }
}

// ---------------------------------------------------------------------------
extern "C" void kernel_launch(void* const* d_in, const int* in_sizes, int n_in,
                              void* d_out, int out_size)
{
    const float* features = (const float*)d_in[0];
    const float* adj      = (const float*)d_in[1];
    const float* W0  = (const float*)d_in[2];
    const float* b0  = (const float*)d_in[3];
    const float* W1  = (const float*)d_in[4];
    const float* b1  = (const float*)d_in[5];
    const float* W2  = (const float*)d_in[6];
    const float* b2  = (const float*)d_in[7];
    const float* C1w = (const float*)d_in[8];
    const float* c1b = (const float*)d_in[9];
    const float* C2w = (const float*)d_in[10];
    const float* c2b = (const float*)d_in[11];
    const float* C3w = (const float*)d_in[12];
    const float* c3b = (const float*)d_in[13];
    float* out = (float*)d_out;

    int H   = in_sizes[3];                 // 256
    int DIN = in_sizes[2] / H;             // 1024
    int N   = in_sizes[0] / DIN;           // 10000

    static cudaStream_t s2 = nullptr;
    static cudaEvent_t  ef = nullptr, ej = nullptr;
    static cudaEvent_t  eA1 = nullptr, eG1 = nullptr, eA2 = nullptr, eG2 = nullptr;
    if (s2 == nullptr) {
        cudaStreamCreateWithFlags(&s2, cudaStreamNonBlocking);
        cudaEventCreateWithFlags(&ef,  cudaEventDisableTiming);
        cudaEventCreateWithFlags(&ej,  cudaEventDisableTiming);
        cudaEventCreateWithFlags(&eA1, cudaEventDisableTiming);
        cudaEventCreateWithFlags(&eG1, cudaEventDisableTiming);
        cudaEventCreateWithFlags(&eA2, cudaEventDisableTiming);
        cudaEventCreateWithFlags(&eG2, cudaEventDisableTiming);
    }

    int tilesM = (N + 63) / 64;            // 157
    int tilesA = (tilesM + 1) / 2;         // 79
    int tilesB = tilesM - tilesA;          // 78
    int NA = tilesA * 64;                  // 5056 rows in half A
    int NB = N - NA;                       // 4944 rows in half B

    dim3 ggrid0 (HDIM / 128, tilesM, 4);   // L0 full: split-K=4
    dim3 ggridHA(HDIM / 128, tilesA, 2);   // HxH rows A
    dim3 ggridHB(HDIM / 128, tilesB, 2);   // HxH rows B
    int total4 = N * HDIM / 4;
    int rblocks = (total4 + 255) / 256;

    // fork: extract on side stream, L0 GEMM on main stream
    cudaEventRecord(ef, 0);
    cudaStreamWaitEvent(s2, ef, 0);
    extract_kernel<<<N, 256, 0, s2>>>(adj, N);
    cudaEventRecord(ej, s2);

    gemm_f32x2_kernel<<<ggrid0, 128>>>(features, W0, N, DIN, 0);
    reduce_kernel<<<rblocks, 256>>>(total4, 4);

    cudaStreamWaitEvent(0, ej, 0);

    // ---- layer 0 aggregate -> layer 1 gemm, pipelined ----
    aggregate_kernel<<<NA, 64>>>(b0, 0);
    cudaEventRecord(eA1, 0);
    aggregate_kernel<<<NB, 64>>>(b0, NA);
    cudaStreamWaitEvent(s2, eA1, 0);
    gemm_f32x2_kernel<<<ggridHA, 128, 0, s2>>>(nullptr, W1, N, H, 0);
    cudaEventRecord(eG1, s2);
    gemm_f32x2_kernel<<<ggridHB, 128>>>(nullptr, W1, N, H, NA);
    cudaStreamWaitEvent(0, eG1, 0);
    reduce_kernel<<<rblocks, 256>>>(total4, 2);

    // ---- layer 1 aggregate -> layer 2 gemm, pipelined ----
    aggregate_kernel<<<NA, 64>>>(b1, 0);
    cudaEventRecord(eA2, 0);
    aggregate_kernel<<<NB, 64>>>(b1, NA);
    cudaStreamWaitEvent(s2, eA2, 0);
    gemm_f32x2_kernel<<<ggridHA, 128, 0, s2>>>(nullptr, W2, N, H, 0);
    cudaEventRecord(eG2, s2);
    gemm_f32x2_kernel<<<ggridHB, 128>>>(nullptr, W2, N, H, NA);
    cudaStreamWaitEvent(0, eG2, 0);
    reduce_kernel<<<rblocks, 256>>>(total4, 2);

    // ---- layer 2 aggregate -> pool -> MLP ----
    aggregate_kernel<<<N, 64>>>(b2, 0);
    pool_partial_kernel<<<POOLB, HDIM>>>(N);
    pool_mlp_kernel<<<1, 512>>>(C1w, c1b, C2w, c2b, C3w, c3b, out, N);
}

// round 17
// speedup vs baseline: 1.0146x; 1.0146x over previous
#include <cuda_runtime.h>
#include <math.h>
#include <float.h>
#include <stdint.h>

// ---------------------------------------------------------------------------
// GCN: sparse-extract adjacency (overlapped with L0 GEMM) -> per layer
//      [split-K f32x2 GEMM (4-way L0, 2-way HxH) w/ cp.async B-tile fill,
//      reduce, sparse aggregate] -> max/mean pool -> MLP head.
// N <= 10000, DIN = 1024, H = 256, NC = 3
// ---------------------------------------------------------------------------

#define MAXN   10112
#define MAXNZ  128
#define HDIM   256
#define POOLB  256

__device__ float g_dinv[MAXN];
__device__ int   g_cnt[MAXN];
__device__ int   g_col[MAXN * MAXNZ];
__device__ float g_val[MAXN * MAXNZ];
__device__ float g_y [MAXN * HDIM];     // split 0 partial -> summed Y
__device__ float g_y2[MAXN * HDIM];     // split 1 partial
__device__ float g_y3[MAXN * HDIM];     // split 2 partial
__device__ float g_y4[MAXN * HDIM];     // split 3 partial
__device__ float g_x [MAXN * HDIM];     // layer activations
__device__ float g_pmax[POOLB * HDIM];
__device__ float g_psum[POOLB * HDIM];

typedef unsigned long long ull;

__device__ __forceinline__ void fma2(ull& d, ull a, ull b)
{
    asm("fma.rn.f32x2 %0, %1, %2, %0;" : "+l"(d) : "l"(a), "l"(b));
}
__device__ __forceinline__ ull pack2(float x, float y)
{
    ull r;
    asm("mov.b64 %0, {%1, %2};" : "=l"(r) : "f"(x), "f"(y));
    return r;
}
__device__ __forceinline__ void unpack2(ull v, float& x, float& y)
{
    asm("mov.b64 {%0, %1}, %2;" : "=f"(x), "=f"(y) : "l"(v));
}
__device__ __forceinline__ uint32_t smem_u32(const void* p)
{
    uint32_t a;
    asm("{ .reg .u64 t; cvta.to.shared.u64 t, %1; cvt.u32.u64 %0, t; }"
        : "=r"(a) : "l"(p));
    return a;
}
__device__ __forceinline__ void cp16(uint32_t s, const void* g)
{
    asm volatile("cp.async.cg.shared.global [%0], [%1], 16;"
                 :: "r"(s), "l"(g) : "memory");
}
__device__ __forceinline__ void cp_commit()
{
    asm volatile("cp.async.commit_group;" ::: "memory");
}
__device__ __forceinline__ void cp_wait0()
{
    asm volatile("cp.async.wait_group 0;" ::: "memory");
}

// ---------------------------------------------------------------------------
// Kernel 1: row scan -> degree (dinv) + nonzero extraction
// ---------------------------------------------------------------------------
__global__ void extract_kernel(const float* __restrict__ adj, int N)
{
    int row = blockIdx.x;
    int tid = threadIdx.x;
    __shared__ int cnt;
    __shared__ float wsum[8];
    if (tid == 0) cnt = 0;
    __syncthreads();

    const float4* a4 = (const float4*)(adj + (size_t)row * N);
    int n4 = N >> 2;
    float sum = 0.0f;

    for (int i = tid; i < n4; i += 256) {
        float4 v = a4[i];
        sum += (v.x + v.y) + (v.z + v.w);
        int j = i << 2;
        if (v.x != 0.0f && j + 0 != row) { int o = atomicAdd(&cnt, 1); if (o < MAXNZ) { g_col[row*MAXNZ+o] = j+0; g_val[row*MAXNZ+o] = v.x; } }
        if (v.y != 0.0f && j + 1 != row) { int o = atomicAdd(&cnt, 1); if (o < MAXNZ) { g_col[row*MAXNZ+o] = j+1; g_val[row*MAXNZ+o] = v.y; } }
        if (v.z != 0.0f && j + 2 != row) { int o = atomicAdd(&cnt, 1); if (o < MAXNZ) { g_col[row*MAXNZ+o] = j+2; g_val[row*MAXNZ+o] = v.z; } }
        if (v.w != 0.0f && j + 3 != row) { int o = atomicAdd(&cnt, 1); if (o < MAXNZ) { g_col[row*MAXNZ+o] = j+3; g_val[row*MAXNZ+o] = v.w; } }
    }
    for (int j = (n4 << 2) + tid; j < N; j += 256) {
        float v = adj[(size_t)row * N + j];
        sum += v;
        if (v != 0.0f && j != row) { int o = atomicAdd(&cnt, 1); if (o < MAXNZ) { g_col[row*MAXNZ+o] = j; g_val[row*MAXNZ+o] = v; } }
    }

    #pragma unroll
    for (int s = 16; s > 0; s >>= 1) sum += __shfl_xor_sync(0xffffffffu, sum, s);
    if ((tid & 31) == 0) wsum[tid >> 5] = sum;
    __syncthreads();
    if (tid == 0) {
        float t = 0.0f;
        #pragma unroll
        for (int w = 0; w < 8; w++) t += wsum[w];
        g_cnt[row]  = cnt < MAXNZ ? cnt : MAXNZ;
        g_dinv[row] = rsqrtf(t + 1.0f);
    }
}

// ---------------------------------------------------------------------------
// Kernel 2: split-K GEMM partials (split count = gridDim.z).
// Tile 64(M) x 128(N), BK=16, 128 threads, per-thread 8x8, double-buffered.
// B tile filled via cp.async (16B chunks, contiguous); A staged via regs.
// ---------------------------------------------------------------------------
#define ABK 16

__global__ void __launch_bounds__(128, 3)
gemm_f32x2_kernel(const float* __restrict__ Aext, const float* __restrict__ B,
                  int M, int Ktot)
{
    __shared__ float As[2][ABK][68];    // [k][m]
    __shared__ float Bs[2][ABK][132];   // [k][n]

    const float* A = Aext ? Aext : g_x;
    int nsplit = gridDim.z;
    int KL   = Ktot / nsplit;
    int kOff = blockIdx.z * KL;
    float* Cout = (blockIdx.z == 0) ? g_y :
                  (blockIdx.z == 1) ? g_y2 :
                  (blockIdx.z == 2) ? g_y3 : g_y4;

    int tid = threadIdx.x;
    int tx = tid & 15;      // cols 4tx..+3 and 64+4tx..+3
    int ty = tid >> 4;      // rows 8ty..+7
    int bm = blockIdx.y * 64;
    int bn = blockIdx.x * 128;

    ull acc[8][4];
    #pragma unroll
    for (int i = 0; i < 8; i++)
        #pragma unroll
        for (int j = 0; j < 4; j++) acc[i][j] = pack2(0.0f, 0.0f);

    // global-load mapping
    int ar = tid >> 1;             // 0..63
    int ak = (tid & 1) << 3;       // 0 or 8
    int gm = bm + ar;
    bool mv = gm < M;
    const float* Arow = A + (size_t)(mv ? gm : 0) * Ktot + kOff;
    const float* Bbase = B + (size_t)kOff * HDIM;

    int bk = tid >> 5;             // 0..3: rows bk, bk+4, bk+8, bk+12
    int bc = (tid & 31) << 2;      // 0..124

    // per-thread smem dst addresses for cp.async (both buffers)
    uint32_t bDst[2][4];
    #pragma unroll
    for (int t = 0; t < 4; t++) {
        bDst[0][t] = smem_u32(&Bs[0][bk + 4*t][bc]);
        bDst[1][t] = smem_u32(&Bs[1][bk + 4*t][bc]);
    }

    // prologue: buffer 0
    {
        #pragma unroll
        for (int t = 0; t < 4; t++)
            cp16(bDst[0][t], &Bbase[(size_t)(bk + 4*t) * HDIM + bn + bc]);
        cp_commit();
        float4 a0 = mv ? *(const float4*)&Arow[ak]     : make_float4(0,0,0,0);
        float4 a1 = mv ? *(const float4*)&Arow[ak + 4] : make_float4(0,0,0,0);
        As[0][ak+0][ar] = a0.x; As[0][ak+1][ar] = a0.y;
        As[0][ak+2][ar] = a0.z; As[0][ak+3][ar] = a0.w;
        As[0][ak+4][ar] = a1.x; As[0][ak+5][ar] = a1.y;
        As[0][ak+6][ar] = a1.z; As[0][ak+7][ar] = a1.w;
        cp_wait0();
    }
    __syncthreads();

    int buf = 0;
    for (int k0 = ABK; k0 < KL; k0 += ABK) {
        // async B fill of the free buffer (overlaps entire compute phase)
        #pragma unroll
        for (int t = 0; t < 4; t++)
            cp16(bDst[buf^1][t], &Bbase[(size_t)(k0 + bk + 4*t) * HDIM + bn + bc]);
        cp_commit();

        float4 aN0 = mv ? *(const float4*)&Arow[k0 + ak]     : make_float4(0,0,0,0);
        float4 aN1 = mv ? *(const float4*)&Arow[k0 + ak + 4] : make_float4(0,0,0,0);

        #pragma unroll
        for (int k = 0; k < ABK; k++) {
            float4 av0 = *(const float4*)&As[buf][k][ty * 8];
            float4 av1 = *(const float4*)&As[buf][k][ty * 8 + 4];
            float4 b0  = *(const float4*)&Bs[buf][k][tx * 4];
            float4 b1  = *(const float4*)&Bs[buf][k][64 + tx * 4];
            ull bp0 = pack2(b0.x, b0.y);
            ull bp1 = pack2(b0.z, b0.w);
            ull bp2 = pack2(b1.x, b1.y);
            ull bp3 = pack2(b1.z, b1.w);
            float arr[8] = {av0.x, av0.y, av0.z, av0.w, av1.x, av1.y, av1.z, av1.w};
            #pragma unroll
            for (int i = 0; i < 8; i++) {
                ull ap = pack2(arr[i], arr[i]);
                fma2(acc[i][0], ap, bp0);
                fma2(acc[i][1], ap, bp1);
                fma2(acc[i][2], ap, bp2);
                fma2(acc[i][3], ap, bp3);
            }
        }

        As[buf^1][ak+0][ar] = aN0.x; As[buf^1][ak+1][ar] = aN0.y;
        As[buf^1][ak+2][ar] = aN0.z; As[buf^1][ak+3][ar] = aN0.w;
        As[buf^1][ak+4][ar] = aN1.x; As[buf^1][ak+5][ar] = aN1.y;
        As[buf^1][ak+6][ar] = aN1.z; As[buf^1][ak+7][ar] = aN1.w;
        cp_wait0();
        __syncthreads();
        buf ^= 1;
    }

    // final tile
    #pragma unroll
    for (int k = 0; k < ABK; k++) {
        float4 av0 = *(const float4*)&As[buf][k][ty * 8];
        float4 av1 = *(const float4*)&As[buf][k][ty * 8 + 4];
        float4 b0  = *(const float4*)&Bs[buf][k][tx * 4];
        float4 b1  = *(const float4*)&Bs[buf][k][64 + tx * 4];
        ull bp0 = pack2(b0.x, b0.y);
        ull bp1 = pack2(b0.z, b0.w);
        ull bp2 = pack2(b1.x, b1.y);
        ull bp3 = pack2(b1.z, b1.w);
        float arr[8] = {av0.x, av0.y, av0.z, av0.w, av1.x, av1.y, av1.z, av1.w};
        #pragma unroll
        for (int i = 0; i < 8; i++) {
            ull ap = pack2(arr[i], arr[i]);
            fma2(acc[i][0], ap, bp0);
            fma2(acc[i][1], ap, bp1);
            fma2(acc[i][2], ap, bp2);
            fma2(acc[i][3], ap, bp3);
        }
    }

    // epilogue
    #pragma unroll
    for (int i = 0; i < 8; i++) {
        int m = bm + ty * 8 + i;
        if (m >= M) continue;
        float o0, o1, o2, o3, o4, o5, o6, o7;
        unpack2(acc[i][0], o0, o1);
        unpack2(acc[i][1], o2, o3);
        unpack2(acc[i][2], o4, o5);
        unpack2(acc[i][3], o6, o7);
        float* dst = &Cout[(size_t)m * HDIM + bn];
        *(float4*)(dst + tx * 4)      = make_float4(o0, o1, o2, o3);
        *(float4*)(dst + 64 + tx * 4) = make_float4(o4, o5, o6, o7);
    }
}

// ---------------------------------------------------------------------------
// Kernel 2b: reduce split-K partials (fixed summation order, deterministic)
// ---------------------------------------------------------------------------
__global__ void reduce_kernel(int total4, int nsplit)
{
    int i = blockIdx.x * blockDim.x + threadIdx.x;
    if (i >= total4) return;
    float4 a = ((const float4*)g_y)[i];
    float4 b = ((const float4*)g_y2)[i];
    if (nsplit == 4) {
        float4 c = ((const float4*)g_y3)[i];
        float4 d = ((const float4*)g_y4)[i];
        a.x = (a.x + b.x) + (c.x + d.x);
        a.y = (a.y + b.y) + (c.y + d.y);
        a.z = (a.z + b.z) + (c.z + d.z);
        a.w = (a.w + b.w) + (c.w + d.w);
    } else {
        a.x += b.x; a.y += b.y; a.z += b.z; a.w += b.w;
    }
    ((float4*)g_y)[i] = a;
}

// ---------------------------------------------------------------------------
// Kernel 3: x'[i] = relu( dinv_i*( dinv_i*Y_i + sum val*dinv_j*Y_j ) + b )
// ---------------------------------------------------------------------------
__global__ void aggregate_kernel(const float* __restrict__ bias)
{
    int i = blockIdx.x;
    int c = threadIdx.x;            // 0..63
    const float4* y4 = (const float4*)g_y;
    float si = g_dinv[i];
    float4 self = y4[(size_t)i * 64 + c];
    float4 acc;
    acc.x = si * self.x; acc.y = si * self.y;
    acc.z = si * self.z; acc.w = si * self.w;

    int cnt = g_cnt[i];
    const int*   cols = &g_col[i * MAXNZ];
    const float* vals = &g_val[i * MAXNZ];

    int e = 0;
    for (; e + 4 <= cnt; e += 4) {
        int   c0 = cols[e],   c1 = cols[e+1], c2 = cols[e+2], c3 = cols[e+3];
        float v0 = vals[e]   * g_dinv[c0];
        float v1 = vals[e+1] * g_dinv[c1];
        float v2 = vals[e+2] * g_dinv[c2];
        float v3 = vals[e+3] * g_dinv[c3];
        float4 y0 = y4[(size_t)c0 * 64 + c];
        float4 y1 = y4[(size_t)c1 * 64 + c];
        float4 y2 = y4[(size_t)c2 * 64 + c];
        float4 y3 = y4[(size_t)c3 * 64 + c];
        acc.x += (v0*y0.x + v1*y1.x) + (v2*y2.x + v3*y3.x);
        acc.y += (v0*y0.y + v1*y1.y) + (v2*y2.y + v3*y3.y);
        acc.z += (v0*y0.z + v1*y1.z) + (v2*y2.z + v3*y3.z);
        acc.w += (v0*y0.w + v1*y1.w) + (v2*y2.w + v3*y3.w);
    }
    for (; e < cnt; e++) {
        int c0 = cols[e];
        float v0 = vals[e] * g_dinv[c0];
        float4 y0 = y4[(size_t)c0 * 64 + c];
        acc.x += v0*y0.x; acc.y += v0*y0.y; acc.z += v0*y0.z; acc.w += v0*y0.w;
    }

    float4 b = ((const float4*)bias)[c];
    float4 r;
    r.x = fmaxf(si*acc.x + b.x, 0.0f);
    r.y = fmaxf(si*acc.y + b.y, 0.0f);
    r.z = fmaxf(si*acc.z + b.z, 0.0f);
    r.w = fmaxf(si*acc.w + b.w, 0.0f);
    ((float4*)g_x)[(size_t)i * 64 + c] = r;
}

// ---------------------------------------------------------------------------
// Kernel 4: partial max/sum pool over rows of g_x (256 blocks)
// ---------------------------------------------------------------------------
__global__ void pool_partial_kernel(int N)
{
    int c = threadIdx.x;
    float mx = -FLT_MAX;
    float sm = 0.0f;
    for (int r = blockIdx.x; r < N; r += POOLB) {
        float v = g_x[(size_t)r * HDIM + c];
        mx = fmaxf(mx, v);
        sm += v;
    }
    g_pmax[blockIdx.x * HDIM + c] = mx;
    g_psum[blockIdx.x * HDIM + c] = sm;
}

// ---------------------------------------------------------------------------
// Kernel 5: finish pooling + MLP head (single block, 512 threads, fixed
// k-splits with deterministic smem reductions)
// ---------------------------------------------------------------------------
__global__ void pool_mlp_kernel(const float* __restrict__ C1w, const float* __restrict__ c1b,
                                const float* __restrict__ C2w, const float* __restrict__ c2b,
                                const float* __restrict__ C3w, const float* __restrict__ c3b,
                                float* __restrict__ out, int N)
{
    __shared__ float g[2 * HDIM];     // [max | mean]
    __shared__ float s0[512];
    __shared__ float s1[512];
    __shared__ float h1[HDIM];
    __shared__ float h2[HDIM / 2];
    int tid = threadIdx.x;
    int c = tid & 255;
    int half = tid >> 8;              // 0..1

    // finish pooling: each half scans 128 partial blocks
    float mx = -FLT_MAX, sm = 0.0f;
    for (int w = half * 128; w < half * 128 + 128; w++) {
        mx = fmaxf(mx, g_pmax[w * HDIM + c]);
        sm += g_psum[w * HDIM + c];
    }
    s0[tid] = mx; s1[tid] = sm;
    __syncthreads();
    if (half == 0) {
        g[c]        = fmaxf(s0[c], s0[c + 256]);
        g[HDIM + c] = (s1[c] + s1[c + 256]) / (float)N;
    }
    __syncthreads();

    // h1 = relu(g @ C1w + c1b): 2-way k-split (256 each)
    {
        float a = 0.0f;
        #pragma unroll 8
        for (int k = half * 256; k < half * 256 + 256; k++)
            a += g[k] * C1w[(size_t)k * HDIM + c];
        s0[tid] = a;
    }
    __syncthreads();
    if (half == 0) h1[c] = fmaxf((s0[c] + s0[c + 256]) + c1b[c], 0.0f);
    __syncthreads();

    // h2 = relu(h1 @ C2w + c2b): 128 cols, 4-way k-split (64 each)
    {
        int c2 = tid & 127, q = tid >> 7;   // q 0..3
        float a2 = 0.0f;
        #pragma unroll 8
        for (int k = q * 64; k < q * 64 + 64; k++)
            a2 += h1[k] * C2w[(size_t)k * (HDIM / 2) + c2];
        s1[q * 128 + c2] = a2;
    }
    __syncthreads();
    if (tid < HDIM / 2)
        h2[tid] = fmaxf(((s1[tid] + s1[128 + tid]) + (s1[256 + tid] + s1[384 + tid]))
                        + c2b[tid], 0.0f);
    __syncthreads();

    // out = h2 @ C3w + c3b
    if (tid < 3) {
        float a3 = c3b[tid];
        #pragma unroll 8
        for (int k = 0; k < HDIM / 2; k++)
            a3 += h2[k] * C3w[(size_t)k * 3 + tid];
        out[tid] = a3;
    }
}

// ---------------------------------------------------------------------------
extern "C" void kernel_launch(void* const* d_in, const int* in_sizes, int n_in,
                              void* d_out, int out_size)
{
    const float* features = (const float*)d_in[0];
    const float* adj      = (const float*)d_in[1];
    const float* W0  = (const float*)d_in[2];
    const float* b0  = (const float*)d_in[3];
    const float* W1  = (const float*)d_in[4];
    const float* b1  = (const float*)d_in[5];
    const float* W2  = (const float*)d_in[6];
    const float* b2  = (const float*)d_in[7];
    const float* C1w = (const float*)d_in[8];
    const float* c1b = (const float*)d_in[9];
    const float* C2w = (const float*)d_in[10];
    const float* c2b = (const float*)d_in[11];
    const float* C3w = (const float*)d_in[12];
    const float* c3b = (const float*)d_in[13];
    float* out = (float*)d_out;

    int H   = in_sizes[3];                 // 256
    int DIN = in_sizes[2] / H;             // 1024
    int N   = in_sizes[0] / DIN;           // 10000

    static cudaStream_t s2 = nullptr;
    static cudaEvent_t  ef = nullptr, ej = nullptr;
    if (s2 == nullptr) {
        cudaStreamCreateWithFlags(&s2, cudaStreamNonBlocking);
        cudaEventCreateWithFlags(&ef, cudaEventDisableTiming);
        cudaEventCreateWithFlags(&ej, cudaEventDisableTiming);
    }

    dim3 ggrid0(HDIM / 128, (N + 63) / 64, 4);   // L0: split-K=4 (K=1024)
    dim3 ggridH(HDIM / 128, (N + 63) / 64, 2);   // HxH: split-K=2 (K=256)
    int total4 = N * HDIM / 4;
    int rblocks = (total4 + 255) / 256;

    // fork: extract on side stream, L0 GEMM on main stream
    cudaEventRecord(ef, 0);
    cudaStreamWaitEvent(s2, ef, 0);
    extract_kernel<<<N, 256, 0, s2>>>(adj, N);
    cudaEventRecord(ej, s2);

    gemm_f32x2_kernel<<<ggrid0, 128>>>(features, W0, N, DIN);
    reduce_kernel<<<rblocks, 256>>>(total4, 4);

    cudaStreamWaitEvent(0, ej, 0);
    aggregate_kernel<<<N, 64>>>(b0);

    gemm_f32x2_kernel<<<ggridH, 128>>>(nullptr, W1, N, H);
    reduce_kernel<<<rblocks, 256>>>(total4, 2);
    aggregate_kernel<<<N, 64>>>(b1);

    gemm_f32x2_kernel<<<ggridH, 128>>>(nullptr, W2, N, H);
    reduce_kernel<<<rblocks, 256>>>(total4, 2);
    aggregate_kernel<<<N, 64>>>(b2);

    pool_partial_kernel<<<POOLB, HDIM>>>(N);
    pool_mlp_kernel<<<1, 512>>>(C1w, c1b, C2w, c2b, C3w, c3b, out, N);
}